// round 1
// baseline (speedup 1.0000x reference)
#include <cuda_runtime.h>
#include <cstdint>

// Problem constants (fixed by the reference).
#define ROWS      8192
#define COLS      8192
#define NUMEL     (1ULL * ROWS * COLS)          // 64M output floats
#define NCODES    (NUMEL / 4)                   // 16M codes (centroid_len = 4)
#define HALF_CODES (NCODES / 2)                 // 8M codes per codebook
#define CB_ENTRIES 512                          // 2 codebooks * 256 centroids (float4 each)

// Each thread processes 4 codes -> one int4 code load, one scale load,
// four float4 (16B) stores = 64B contiguous output per thread.
__global__ __launch_bounds__(256) void dequant_kernel(
    const float4* __restrict__ codebooks,   // [512] float4
    const float*  __restrict__ scales,      // [NUMEL/64]
    const int4*   __restrict__ codes4,      // [NCODES/4]
    float4*       __restrict__ out4)        // [NCODES]
{
    __shared__ float4 s_cb[CB_ENTRIES];
    // Stage the 8KB codebook into shared memory (conflict-free linear copy).
    for (int i = threadIdx.x; i < CB_ENTRIES; i += blockDim.x)
        s_cb[i] = codebooks[i];
    __syncthreads();

    const long long t = (long long)blockIdx.x * blockDim.x + threadIdx.x;   // [0, NCODES/4)
    const long long code_base = t * 4;                                      // first code index

    // All 4 codes in this thread share one scale: (4t+k)/16 == t/4 for k in 0..3.
    const float s = __ldg(&scales[t >> 2]);

    // Codebook half: codes [0, 8M) -> codebook 0, [8M, 16M) -> codebook 1.
    // HALF_CODES is a multiple of 4, so all 4 codes share the same half.
    const int cb_off = (code_base >= (long long)HALF_CODES) ? 256 : 0;

    const int4 c = __ldg(&codes4[t]);

    float4 v0 = s_cb[cb_off + c.x];
    float4 v1 = s_cb[cb_off + c.y];
    float4 v2 = s_cb[cb_off + c.z];
    float4 v3 = s_cb[cb_off + c.w];

    v0.x *= s; v0.y *= s; v0.z *= s; v0.w *= s;
    v1.x *= s; v1.y *= s; v1.z *= s; v1.w *= s;
    v2.x *= s; v2.y *= s; v2.z *= s; v2.w *= s;
    v3.x *= s; v3.y *= s; v3.z *= s; v3.w *= s;

    float4* o = out4 + code_base;
    o[0] = v0;
    o[1] = v1;
    o[2] = v2;
    o[3] = v3;
}

extern "C" void kernel_launch(void* const* d_in, const int* in_sizes, int n_in,
                              void* d_out, int out_size)
{
    // metadata order: codebooks [2,256,4] f32, scales [1M,1] f32, codes [2,8M] i32, rows, columns
    const float4* codebooks = (const float4*)d_in[0];
    const float*  scales    = (const float*)d_in[1];
    const int4*   codes4    = (const int4*)d_in[2];
    float4*       out4      = (float4*)d_out;

    const long long n_threads = NCODES / 4;     // 4M threads
    const int block = 256;
    const int grid = (int)(n_threads / block);  // 16384 blocks (exact)

    dequant_kernel<<<grid, block>>>(codebooks, scales, codes4, out4);
}

// round 2
// speedup vs baseline: 1.3491x; 1.3491x over previous
#include <cuda_runtime.h>
#include <cstdint>

// Problem constants (fixed by the reference).
#define ROWS       8192
#define COLS       8192
#define NUMEL      (1ULL * ROWS * COLS)          // 64M output floats
#define NCODES     (NUMEL / 4)                   // 16M codes (centroid_len = 4)
#define CB_ENTRIES 512                           // 2 codebooks * 256 centroids (float4 each)

#define BLOCK      256
#define CODES_PER_THREAD 8
#define TILE_CODES (BLOCK * CODES_PER_THREAD)    // 2048
#define NTILES     ((int)(NCODES / TILE_CODES))  // 8192 (exact)

// Persistent-style kernel: codebook staged to smem once per block, then
// grid-stride over tiles. Interleaved per-thread assignment (t, t+256, ...)
// keeps every global load/store instruction perfectly coalesced.
__global__ __launch_bounds__(BLOCK) void dequant_kernel(
    const float4* __restrict__ codebooks,   // [512] float4
    const float*  __restrict__ scales,      // [NUMEL/64]
    const int*    __restrict__ codes,       // [NCODES]
    float4*       __restrict__ out4)        // [NCODES]
{
    __shared__ float4 s_cb[CB_ENTRIES];
    for (int i = threadIdx.x; i < CB_ENTRIES; i += BLOCK)
        s_cb[i] = codebooks[i];
    __syncthreads();

    const int t = threadIdx.x;

    for (int tile = blockIdx.x; tile < NTILES; tile += gridDim.x) {
        const long long base = (long long)tile * TILE_CODES;
        // Codebook half: first 8M codes -> cb 0, rest -> cb 1.
        // NTILES/2 tiles fall entirely in the first half (8M / 2048 = 4096).
        const int cb_off = (tile >= (NTILES / 2)) ? 256 : 0;

        const int*   cp = codes  + base;
        const float* sp = scales + (base >> 4);   // one scale per 16 codes
        float4*      op = out4   + base;

        int   c[CODES_PER_THREAD];
        float s[CODES_PER_THREAD];

        // Front-batch all global loads (MLP ~16, each instruction coalesced).
        #pragma unroll
        for (int k = 0; k < CODES_PER_THREAD; k++)
            c[k] = __ldg(cp + k * BLOCK + t);
        #pragma unroll
        for (int k = 0; k < CODES_PER_THREAD; k++)
            s[k] = __ldg(sp + ((k * BLOCK + t) >> 4));

        // Gather from smem codebook, scale, store (coalesced STG.128).
        #pragma unroll
        for (int k = 0; k < CODES_PER_THREAD; k++) {
            float4 v = s_cb[cb_off + c[k]];
            v.x *= s[k]; v.y *= s[k]; v.z *= s[k]; v.w *= s[k];
            op[k * BLOCK + t] = v;
        }
    }
}

extern "C" void kernel_launch(void* const* d_in, const int* in_sizes, int n_in,
                              void* d_out, int out_size)
{
    // metadata order: codebooks [2,256,4] f32, scales [1M,1] f32, codes [2,8M] i32, rows, columns
    const float4* codebooks = (const float4*)d_in[0];
    const float*  scales    = (const float*)d_in[1];
    const int*    codes     = (const int*)d_in[2];
    float4*       out4      = (float4*)d_out;

    // ~4 blocks per SM (152 SMs on GB300) -> one resident wave, grid-stride.
    int grid = 152 * 4;
    if (grid > NTILES) grid = NTILES;

    dequant_kernel<<<grid, BLOCK>>>(codebooks, scales, codes, out4);
}

// round 3
// speedup vs baseline: 1.3698x; 1.0153x over previous
#include <cuda_runtime.h>
#include <cstdint>

// Problem constants (fixed by the reference).
#define ROWS       8192
#define COLS       8192
#define NUMEL      (1ULL * ROWS * COLS)          // 64M output floats
#define NCODES     (NUMEL / 4)                   // 16M codes (centroid_len = 4)
#define CB_ENTRIES 512                           // 2 codebooks * 256 centroids (float4 each)

#define BLOCK      256
#define BLOCKS_PER_SM 8
#define CODES_PER_THREAD 8
#define TILE_CODES (BLOCK * CODES_PER_THREAD)    // 2048
#define NTILES     ((int)(NCODES / TILE_CODES))  // 8192 (exact)

// Persistent-style kernel: codebook staged to smem once per block, then
// grid-stride over tiles. Interleaved per-thread assignment (t, t+256, ...)
// keeps every global load/store instruction perfectly coalesced.
// __launch_bounds__(256, 8) pins regs <= 32 so 8 blocks (64 warps) fit per SM.
__global__ __launch_bounds__(BLOCK, BLOCKS_PER_SM) void dequant_kernel(
    const float4* __restrict__ codebooks,   // [512] float4
    const float*  __restrict__ scales,      // [NUMEL/64]
    const int*    __restrict__ codes,       // [NCODES]
    float4*       __restrict__ out4)        // [NCODES]
{
    __shared__ float4 s_cb[CB_ENTRIES];
    for (int i = threadIdx.x; i < CB_ENTRIES; i += BLOCK)
        s_cb[i] = codebooks[i];
    __syncthreads();

    const int t = threadIdx.x;

    for (int tile = blockIdx.x; tile < NTILES; tile += gridDim.x) {
        const long long base = (long long)tile * TILE_CODES;
        // Codebook half: first 8M codes -> cb 0, rest -> cb 1.
        // 8M / 2048 = 4096 tiles fall entirely in the first half.
        const int cb_off = (tile >= (NTILES / 2)) ? 256 : 0;

        const int*   cp = codes  + base;
        const float* sp = scales + (base >> 4);   // one scale per 16 codes
        float4*      op = out4   + base;

        int   c[CODES_PER_THREAD];
        float s[CODES_PER_THREAD];

        // Front-batch all global loads (MLP ~16, each instruction coalesced).
        #pragma unroll
        for (int k = 0; k < CODES_PER_THREAD; k++)
            c[k] = __ldg(cp + k * BLOCK + t);
        #pragma unroll
        for (int k = 0; k < CODES_PER_THREAD; k++)
            s[k] = __ldg(sp + ((k * BLOCK + t) >> 4));

        // Gather from smem codebook, scale, store (coalesced STG.128).
        #pragma unroll
        for (int k = 0; k < CODES_PER_THREAD; k++) {
            float4 v = s_cb[cb_off + c[k]];
            v.x *= s[k]; v.y *= s[k]; v.z *= s[k]; v.w *= s[k];
            op[k * BLOCK + t] = v;
        }
    }
}

extern "C" void kernel_launch(void* const* d_in, const int* in_sizes, int n_in,
                              void* d_out, int out_size)
{
    // metadata order: codebooks [2,256,4] f32, scales [1M,1] f32, codes [2,8M] i32, rows, columns
    const float4* codebooks = (const float4*)d_in[0];
    const float*  scales    = (const float*)d_in[1];
    const int*    codes     = (const int*)d_in[2];
    float4*       out4      = (float4*)d_out;

    // 8 blocks per SM (152 SMs on GB300) -> 64 warps/SM resident, grid-stride.
    int grid = 152 * BLOCKS_PER_SM;   // 1216
    if (grid > NTILES) grid = NTILES;

    dequant_kernel<<<grid, BLOCK>>>(codebooks, scales, codes, out4);
}